// round 1
// baseline (speedup 1.0000x reference)
#include <cuda_runtime.h>

// ---------------------------------------------------------------------------
// VQMetaBaseline: z_e = [x_shot;x_query] @ enc_w + enc_b  ->  nearest codebook
// index (argmin squared L2)  ->  q = codebook column  ->  cosine proto logits.
// Forward output depends on z_e ONLY through argmin indices (straight-through),
// so fp32-accurate GEMM guarantees index parity with the fp32 reference.
// ---------------------------------------------------------------------------

#define IN_DIM 49152
#define DEMB   512
#define NK     512            // codebook entries
#define MROWS  400            // 100 shot + 300 query rows
#define NSHOT  100

#define BM 64
#define BN 64
#define BK 16
#define SPLITS 16
#define KSPLIT (IN_DIM / SPLITS)   // 3072

// scratch (static device globals; no runtime allocation allowed)
__device__ float g_part[SPLITS * MROWS * DEMB];   // split-K partials (13.1 MB)
__device__ float g_ze[MROWS * DEMB];
__device__ int   g_idx[MROWS];
__device__ float g_proto[20 * DEMB];              // normalized prototypes [B*W, D]

// ---- packed fp32x2 helpers (Blackwell sm_100+; identical rounding to 2x fmaf)
__device__ __forceinline__ unsigned long long pack2(float x) {
    unsigned long long r;
    asm("mov.b64 %0, {%1, %1};" : "=l"(r) : "f"(x));
    return r;
}
__device__ __forceinline__ void fma2(unsigned long long& d,
                                     unsigned long long a,
                                     unsigned long long b) {
    asm("fma.rn.f32x2 %0, %1, %2, %0;" : "+l"(d) : "l"(a), "l"(b));
}
__device__ __forceinline__ float lo32(unsigned long long v) {
    return __uint_as_float((unsigned)(v & 0xffffffffull));
}
__device__ __forceinline__ float hi32(unsigned long long v) {
    return __uint_as_float((unsigned)(v >> 32));
}

// ---------------------------------------------------------------------------
// Kernel 1: split-K fp32 GEMM partials.  grid = (N/BN=8, ceil(M/BM)=7, SPLITS)
// A row r: r<100 -> x_shot, else x_query (virtual concat). 256 threads,
// 4x4 register tile per thread via f32x2 packed FMA (8 fma2 per k-step).
// ---------------------------------------------------------------------------
__global__ __launch_bounds__(256) void gemm_partial(
    const float* __restrict__ xs, const float* __restrict__ xq,
    const float* __restrict__ W)
{
    __shared__ float As[BK][BM];   // transposed A tile
    __shared__ float Bs[BK][BN];

    const int t  = threadIdx.x;
    const int n0 = blockIdx.x * BN;
    const int m0 = blockIdx.y * BM;
    const int sp = blockIdx.z;
    const int k0 = sp * KSPLIT;
    const int kend = k0 + KSPLIT;

    const int tx = t & 15;         // output col group
    const int ty = t >> 4;         // output row group

    // A load mapping: each thread one float4 (row = t/4, cols ac..ac+3)
    const int ar = t >> 2;
    const int ac = (t & 3) << 2;
    const int grow = m0 + ar;
    const float* arow = 0;
    if (grow < NSHOT)      arow = xs + (size_t)grow * IN_DIM;
    else if (grow < MROWS) arow = xq + (size_t)(grow - NSHOT) * IN_DIM;

    // B load mapping: each thread one float4 (row = t/16, cols bc..bc+3)
    const int br = t >> 4;
    const int bc = (t & 15) << 2;

    unsigned long long acc[4][2];
#pragma unroll
    for (int i = 0; i < 4; i++) { acc[i][0] = 0ull; acc[i][1] = 0ull; }

    float4 av = arow ? *(const float4*)(arow + k0 + ac) : make_float4(0.f,0.f,0.f,0.f);
    float4 bv = *(const float4*)(W + (size_t)(k0 + br) * DEMB + n0 + bc);

    for (int k = k0; k < kend; k += BK) {
        As[ac + 0][ar] = av.x;
        As[ac + 1][ar] = av.y;
        As[ac + 2][ar] = av.z;
        As[ac + 3][ar] = av.w;
        *(float4*)&Bs[br][bc] = bv;
        __syncthreads();

        const int kn = k + BK;
        if (kn < kend) {   // register prefetch of next tile
            av = arow ? *(const float4*)(arow + kn + ac) : make_float4(0.f,0.f,0.f,0.f);
            bv = *(const float4*)(W + (size_t)(kn + br) * DEMB + n0 + bc);
        }

#pragma unroll
        for (int kk = 0; kk < BK; kk++) {
            float4  a  = *(const float4*)&As[kk][ty << 2];
            double2 bd = *(const double2*)&Bs[kk][tx << 2];
            unsigned long long b0 = __double_as_longlong(bd.x);
            unsigned long long b1 = __double_as_longlong(bd.y);
            unsigned long long a0 = pack2(a.x);
            unsigned long long a1 = pack2(a.y);
            unsigned long long a2 = pack2(a.z);
            unsigned long long a3 = pack2(a.w);
            fma2(acc[0][0], a0, b0); fma2(acc[0][1], a0, b1);
            fma2(acc[1][0], a1, b0); fma2(acc[1][1], a1, b1);
            fma2(acc[2][0], a2, b0); fma2(acc[2][1], a2, b1);
            fma2(acc[3][0], a3, b0); fma2(acc[3][1], a3, b1);
        }
        __syncthreads();
    }

#pragma unroll
    for (int r = 0; r < 4; r++) {
        const int gm = m0 + (ty << 2) + r;
        if (gm < MROWS) {
            float4 o;
            o.x = lo32(acc[r][0]); o.y = hi32(acc[r][0]);
            o.z = lo32(acc[r][1]); o.w = hi32(acc[r][1]);
            *(float4*)&g_part[((size_t)sp * MROWS + gm) * DEMB + n0 + (tx << 2)] = o;
        }
    }
}

// ---------------------------------------------------------------------------
// Kernel 2: deterministic split-K reduction + bias  -> g_ze
// ---------------------------------------------------------------------------
__global__ void reduce_bias(const float* __restrict__ bias)
{
    const int i = blockIdx.x * blockDim.x + threadIdx.x;
    if (i >= MROWS * DEMB) return;
    float s = 0.f;
#pragma unroll
    for (int p = 0; p < SPLITS; p++) s += g_part[p * (MROWS * DEMB) + i];
    g_ze[i] = s + bias[i & (DEMB - 1)];
}

// ---------------------------------------------------------------------------
// Kernel 3: nearest codebook entry per row.
// argmin_k ||z - c_k||^2  ==  argmax_k ( z.c_k - 0.5*||c_k||^2 ), tie -> min k
// 8 rows per block; thread t owns codebook column k=t (coalesced codebook read).
// ---------------------------------------------------------------------------
__global__ __launch_bounds__(512) void nearest_kernel(const float* __restrict__ cb)
{
    __shared__ float zs[8][DEMB];
    __shared__ float red[512];
    __shared__ int   redi[512];

    const int t  = threadIdx.x;
    const int r0 = blockIdx.x * 8;

#pragma unroll
    for (int g = 0; g < 8; g++) zs[g][t] = g_ze[(r0 + g) * DEMB + t];
    __syncthreads();

    float s[8];
#pragma unroll
    for (int g = 0; g < 8; g++) s[g] = 0.f;
    float cn = 0.f;

#pragma unroll 4
    for (int d = 0; d < DEMB; d++) {
        const float c = cb[d * NK + t];     // coalesced: consecutive k per thread
        cn = fmaf(c, c, cn);
#pragma unroll
        for (int g = 0; g < 8; g++) s[g] = fmaf(zs[g][d], c, s[g]);
    }

    for (int g = 0; g < 8; g++) {
        red[t]  = s[g] - 0.5f * cn;
        redi[t] = t;
        __syncthreads();
        for (int off = 256; off > 0; off >>= 1) {
            if (t < off) {
                const float o  = red[t + off];
                const int   oi = redi[t + off];
                if (o > red[t] || (o == red[t] && oi < redi[t])) {
                    red[t] = o; redi[t] = oi;
                }
            }
            __syncthreads();
        }
        if (t == 0) g_idx[r0 + g] = redi[0];
        __syncthreads();
    }
}

// ---------------------------------------------------------------------------
// Kernel 4: prototypes: mean of 5 quantized shot vectors, L2-normalized.
// block = (b*5 + w), thread t = dim d.  q[r][d] = cb[d*NK + idx[r]].
// ---------------------------------------------------------------------------
__global__ __launch_bounds__(512) void proto_kernel(const float* __restrict__ cb)
{
    const int bw = blockIdx.x;   // 0..19
    const int t  = threadIdx.x;  // dim
    float p = 0.f;
#pragma unroll
    for (int s = 0; s < 5; s++) {
        const int idx = g_idx[bw * 5 + s];
        p += cb[(size_t)t * NK + idx];
    }
    p *= 0.2f;

    __shared__ float red[512];
    red[t] = p * p;
    __syncthreads();
    for (int off = 256; off > 0; off >>= 1) {
        if (t < off) red[t] += red[t + off];
        __syncthreads();
    }
    g_proto[bw * DEMB + t] = p * rsqrtf(red[0]);
}

// ---------------------------------------------------------------------------
// Kernel 5: logits[b,q,w] = temp * (q_query_norm . proto_norm)
// block = (b*75 + q), 512 threads over dims.
// ---------------------------------------------------------------------------
__global__ __launch_bounds__(512) void logits_kernel(
    const float* __restrict__ cb, const float* __restrict__ tptr,
    float* __restrict__ out)
{
    const int bq = blockIdx.x;   // 0..299
    const int t  = threadIdx.x;
    const int b  = bq / 75;

    const int idx = g_idx[NSHOT + bq];
    const float v = cb[(size_t)t * NK + idx];

    __shared__ float red[512];
    red[t] = v * v;
    __syncthreads();
    for (int off = 256; off > 0; off >>= 1) {
        if (t < off) red[t] += red[t + off];
        __syncthreads();
    }
    const float vn = v * rsqrtf(red[0]);
    const float temp = *tptr;

    for (int w = 0; w < 5; w++) {
        __syncthreads();   // protect red[] reuse
        red[t] = vn * g_proto[(b * 5 + w) * DEMB + t];
        __syncthreads();
        for (int off = 256; off > 0; off >>= 1) {
            if (t < off) red[t] += red[t + off];
            __syncthreads();
        }
        if (t == 0) out[bq * 5 + w] = red[0] * temp;
    }
}

// ---------------------------------------------------------------------------
extern "C" void kernel_launch(void* const* d_in, const int* in_sizes, int n_in,
                              void* d_out, int out_size)
{
    const float* xs   = (const float*)d_in[0];  // x_shot  [100, 49152]
    const float* xq   = (const float*)d_in[1];  // x_query [300, 49152]
    const float* W    = (const float*)d_in[2];  // enc_w   [49152, 512]
    const float* bias = (const float*)d_in[3];  // enc_b   [512]
    const float* cb   = (const float*)d_in[4];  // codebook [512, 512] (D,K)
    const float* temp = (const float*)d_in[5];  // scalar
    float* out = (float*)d_out;                 // [4,75,5]

    dim3 ggrid(DEMB / BN, (MROWS + BM - 1) / BM, SPLITS);  // (8,7,16)
    gemm_partial<<<ggrid, 256>>>(xs, xq, W);
    reduce_bias<<<(MROWS * DEMB + 255) / 256, 256>>>(bias);
    nearest_kernel<<<MROWS / 8, 512>>>(cb);
    proto_kernel<<<20, 512>>>(cb);
    logits_kernel<<<300, 512>>>(cb, temp, out);
}

// round 3
// speedup vs baseline: 1.9323x; 1.9323x over previous
#include <cuda_runtime.h>
#include <cuda_bf16.h>
#include <cstdint>

// ============================================================================
// VQMetaBaseline via mma.sync bf16 (compute_103-safe; no tcgen05):
// z_e = X @ W + b with bf16 hi/lo Dekker split, 3 exact-product passes
// (hi*hi + hi*lo + lo*hi) accumulated in fp32 -> argmin-index parity with the
// fp32 reference. Then nearest-codebook, prototypes, cosine logits.
// ============================================================================

#define IN_DIM 49152
#define NDIM   512
#define NK     512
#define MROWS  400
#define MPAD   512
#define NSHOT  100

// GEMM tiling
#define BM 128
#define BN 128
#define BK 32
#define STAGES 4
#define STG_BYTES 16384            // A 8KB + B 8KB per stage
#define SMEM_GEMM (STAGES * STG_BYTES)   // 64 KB

// split-K: 3 phases (hihi, hilo, lohi) x 6 sub-splits
#define SUBSPLITS 6
#define TOTSPLITS 18
#define KSPLIT (IN_DIM / SUBSPLITS)      // 8192
#define NT (KSPLIT / BK)                 // 256 k-tiles per CTA

// ---- scratch (static device globals; no runtime allocation) ----------------
__device__ __align__(128) __nv_bfloat16 gAhi[(size_t)MPAD * IN_DIM];
__device__ __align__(128) __nv_bfloat16 gAlo[(size_t)MPAD * IN_DIM];
__device__ __align__(128) __nv_bfloat16 gBhi[(size_t)NDIM * IN_DIM];
__device__ __align__(128) __nv_bfloat16 gBlo[(size_t)NDIM * IN_DIM];
__device__ float g_part[(size_t)TOTSPLITS * MPAD * NDIM];
__device__ float g_ze[MROWS * NDIM];
__device__ int   g_idx[MROWS];
__device__ float g_proto[20 * NDIM];

// ---- helpers ----------------------------------------------------------------
__device__ __forceinline__ uint32_t smem_u32(const void* p) {
    uint32_t a;
    asm("{ .reg .u64 t; cvta.to.shared.u64 t, %1; cvt.u32.u64 %0, t; }"
        : "=r"(a) : "l"(p));
    return a;
}
__device__ __forceinline__ void cp16(uint32_t dst, const void* src) {
    asm volatile("cp.async.cg.shared.global [%0], [%1], 16;"
                 :: "r"(dst), "l"(src) : "memory");
}
#define CP_COMMIT() asm volatile("cp.async.commit_group;" ::: "memory")
#define CP_WAIT2()  asm volatile("cp.async.wait_group 2;" ::: "memory")

__device__ __forceinline__ void ldsm4(uint32_t& r0, uint32_t& r1,
                                      uint32_t& r2, uint32_t& r3, uint32_t a) {
    asm volatile("ldmatrix.sync.aligned.m8n8.x4.shared.b16 {%0,%1,%2,%3}, [%4];"
                 : "=r"(r0), "=r"(r1), "=r"(r2), "=r"(r3) : "r"(a));
}
__device__ __forceinline__ void mma16816(float* c, const uint32_t* a,
                                         const uint32_t* b) {
    asm volatile(
        "mma.sync.aligned.m16n8k16.row.col.f32.bf16.bf16.f32 "
        "{%0,%1,%2,%3},{%4,%5,%6,%7},{%8,%9},{%0,%1,%2,%3};"
        : "+f"(c[0]), "+f"(c[1]), "+f"(c[2]), "+f"(c[3])
        : "r"(a[0]), "r"(a[1]), "r"(a[2]), "r"(a[3]), "r"(b[0]), "r"(b[1]));
}

// smem tile offset: 128 rows x 64B (32 bf16), XOR swizzle -> conflict-free
// ldmatrix (8-lane phases hit 8 distinct 16B banks groups)
__device__ __forceinline__ uint32_t toff(int r, int c) {
    return (uint32_t)(r * 64 + ((c ^ ((r >> 1) & 3)) << 4));
}

__device__ __forceinline__ void fsplit(float x, __nv_bfloat16& h, __nv_bfloat16& l) {
    h = __float2bfloat16_rn(x);
    l = __float2bfloat16_rn(x - __bfloat162float(h));
}
__device__ __forceinline__ uint32_t pack2bf(__nv_bfloat16 a, __nv_bfloat16 b) {
    __nv_bfloat162 v(a, b);
    return *reinterpret_cast<uint32_t*>(&v);
}

// ============================================================================
// conv_a: [xs;xq] fp32 -> gAhi/gAlo bf16, rows 400..511 zero-padded
// ============================================================================
__global__ __launch_bounds__(256) void conv_a(const float* __restrict__ xs,
                                              const float* __restrict__ xq) {
    size_t e = ((size_t)blockIdx.x * 256 + threadIdx.x) * 4;
    if (e >= (size_t)MPAD * IN_DIM) return;
    int row = (int)(e / IN_DIM);
    int col = (int)(e % IN_DIM);
    float4 v = make_float4(0.f, 0.f, 0.f, 0.f);
    if (row < NSHOT)      v = *(const float4*)(xs + (size_t)row * IN_DIM + col);
    else if (row < MROWS) v = *(const float4*)(xq + (size_t)(row - NSHOT) * IN_DIM + col);
    __nv_bfloat16 h0,h1,h2,h3,l0,l1,l2,l3;
    fsplit(v.x,h0,l0); fsplit(v.y,h1,l1); fsplit(v.z,h2,l2); fsplit(v.w,h3,l3);
    *(uint2*)&gAhi[e] = make_uint2(pack2bf(h0,h1), pack2bf(h2,h3));
    *(uint2*)&gAlo[e] = make_uint2(pack2bf(l0,l1), pack2bf(l2,l3));
}

// ============================================================================
// conv_b: enc_w [K,N] fp32 -> gBhi/gBlo [N,K] bf16 (transpose via smem tile)
// ============================================================================
__global__ __launch_bounds__(256) void conv_b(const float* __restrict__ W) {
    __shared__ float ts[32][33];
    const int k0 = blockIdx.x << 5;
    const int n0 = blockIdx.y << 5;
    const int t  = threadIdx.x;
    {
        int r = t >> 3, c = (t & 7) << 2;
        float4 v = *(const float4*)(W + (size_t)(k0 + r) * NDIM + n0 + c);
        ts[r][c] = v.x; ts[r][c+1] = v.y; ts[r][c+2] = v.z; ts[r][c+3] = v.w;
    }
    __syncthreads();
    int n = t >> 3, kq = (t & 7) << 2;
    __nv_bfloat16 h[4], l[4];
#pragma unroll
    for (int i = 0; i < 4; i++) fsplit(ts[kq + i][n], h[i], l[i]);
    size_t o = (size_t)(n0 + n) * IN_DIM + k0 + kq;
    *(uint2*)&gBhi[o] = make_uint2(pack2bf(h[0],h[1]), pack2bf(h[2],h[3]));
    *(uint2*)&gBlo[o] = make_uint2(pack2bf(l[0],l[1]), pack2bf(l[2],l[3]));
}

// ============================================================================
// HMMA GEMM: g_part[sp] = A_ph @ B_ph^T over k slice
// grid (BN tiles=4, BM tiles=4, 18 splits), 256 threads, 8 warps (4M x 2N).
// ============================================================================
__global__ __launch_bounds__(256, 2) void gemm_hmma() {
    extern __shared__ char smem[];
    const uint32_t sbase = smem_u32(smem);
    const int t = threadIdx.x;
    const int wid = t >> 5, lane = t & 31;

    const int n0 = blockIdx.x * BN;
    const int m0 = blockIdx.y * BM;
    const int sp = blockIdx.z;
    const int phase = sp / SUBSPLITS;            // 0: hi*hi  1: hi*lo  2: lo*hi
    const size_t ksub = (size_t)(sp % SUBSPLITS) * KSPLIT;

    const __nv_bfloat16* __restrict__ A = (phase == 2) ? gAlo : gAhi;
    const __nv_bfloat16* __restrict__ B = (phase == 1) ? gBlo : gBhi;

    // ---- loader mapping: thread loads 2 A chunks + 2 B chunks of 16B per stage
    const int lr = t >> 2;          // tile row 0..63
    const int lc = t & 3;           // 16B chunk 0..3
    const uint32_t dA1 = toff(lr, lc),        dA2 = toff(lr + 64, lc);
    const uint32_t dB1 = toff(lr, lc) + 8192, dB2 = toff(lr + 64, lc) + 8192;
    const __nv_bfloat16* pA1 = A + (size_t)(m0 + lr) * IN_DIM + ksub + lc * 8;
    const __nv_bfloat16* pA2 = pA1 + (size_t)64 * IN_DIM;
    const __nv_bfloat16* pB1 = B + (size_t)(n0 + lr) * IN_DIM + ksub + lc * 8;
    const __nv_bfloat16* pB2 = pB1 + (size_t)64 * IN_DIM;

    // ---- compute mapping: warp (wm, wn) owns 32x64 of C
    const int wm = wid >> 1, wn = wid & 1;
    const int fr = lane & 15, fc = lane >> 4;
    uint32_t aoff[2][2], boff[4][2];
#pragma unroll
    for (int mh = 0; mh < 2; mh++)
#pragma unroll
        for (int ks = 0; ks < 2; ks++)
            aoff[mh][ks] = toff(wm * 32 + mh * 16 + fr, ks * 2 + fc);
#pragma unroll
    for (int p = 0; p < 4; p++)
#pragma unroll
        for (int ks = 0; ks < 2; ks++)
            boff[p][ks] = 8192 + toff(wn * 64 + p * 16 + fr, ks * 2 + fc);

    float c[2][8][4];
#pragma unroll
    for (int i = 0; i < 2; i++)
#pragma unroll
        for (int j = 0; j < 8; j++)
#pragma unroll
            for (int k = 0; k < 4; k++) c[i][j][k] = 0.f;

    // ---- prologue: fill stages 0..2
#pragma unroll
    for (int s = 0; s < STAGES - 1; s++) {
        const uint32_t sb = sbase + s * STG_BYTES;
        const size_t ko = (size_t)s * BK;
        cp16(sb + dA1, pA1 + ko); cp16(sb + dA2, pA2 + ko);
        cp16(sb + dB1, pB1 + ko); cp16(sb + dB2, pB2 + ko);
        CP_COMMIT();
    }

    // ---- main loop
    for (int kt = 0; kt < NT; ++kt) {
        CP_WAIT2();
        __syncthreads();

        if (kt + STAGES - 1 < NT) {
            const uint32_t sb = sbase + ((kt + STAGES - 1) & (STAGES - 1)) * STG_BYTES;
            const size_t ko = (size_t)(kt + STAGES - 1) * BK;
            cp16(sb + dA1, pA1 + ko); cp16(sb + dA2, pA2 + ko);
            cp16(sb + dB1, pB1 + ko); cp16(sb + dB2, pB2 + ko);
        }
        CP_COMMIT();

        const uint32_t sb = sbase + (kt & (STAGES - 1)) * STG_BYTES;
#pragma unroll
        for (int ks = 0; ks < 2; ks++) {
            uint32_t a0[4], a1[4];
            ldsm4(a0[0], a0[1], a0[2], a0[3], sb + aoff[0][ks]);
            ldsm4(a1[0], a1[1], a1[2], a1[3], sb + aoff[1][ks]);
#pragma unroll
            for (int p = 0; p < 4; p++) {
                uint32_t r0, r1, r2, r3;
                ldsm4(r0, r1, r2, r3, sb + boff[p][ks]);
                uint32_t b0[2] = { r0, r2 };
                uint32_t b1[2] = { r1, r3 };
                mma16816(c[0][2*p],     a0, b0);
                mma16816(c[1][2*p],     a1, b0);
                mma16816(c[0][2*p + 1], a0, b1);
                mma16816(c[1][2*p + 1], a1, b1);
            }
        }
    }

    // ---- epilogue: direct fp32 stores of partials
    float* base = g_part + (size_t)sp * MPAD * NDIM;
    const int row0 = m0 + wm * 32 + (lane >> 2);
    const int col0 = n0 + wn * 64 + (lane & 3) * 2;
#pragma unroll
    for (int mi = 0; mi < 2; mi++)
#pragma unroll
        for (int j = 0; j < 8; j++) {
            const int r = row0 + mi * 16;
            const int cc = col0 + j * 8;
            *(float2*)&base[(size_t)r * NDIM + cc]       = make_float2(c[mi][j][0], c[mi][j][1]);
            *(float2*)&base[(size_t)(r + 8) * NDIM + cc] = make_float2(c[mi][j][2], c[mi][j][3]);
        }
}

// ============================================================================
// split-K reduce + bias (deterministic order)
// ============================================================================
__global__ void reduce_bias(const float* __restrict__ bias) {
    const int i = blockIdx.x * blockDim.x + threadIdx.x;
    if (i >= MROWS * NDIM) return;
    const int m = i >> 9, n = i & (NDIM - 1);
    float s = 0.f;
#pragma unroll
    for (int p = 0; p < TOTSPLITS; p++)
        s += g_part[((size_t)p * MPAD + m) * NDIM + n];
    g_ze[i] = s + bias[n];
}

// ============================================================================
// nearest codebook: argmax_k (z.c_k - 0.5||c_k||^2), tie -> min k
// ============================================================================
__global__ __launch_bounds__(512) void nearest_kernel(const float* __restrict__ cb) {
    __shared__ float zs[8][NDIM];
    __shared__ float red[512];
    __shared__ int   redi[512];
    const int t = threadIdx.x;
    const int r0 = blockIdx.x * 8;
#pragma unroll
    for (int g = 0; g < 8; g++) zs[g][t] = g_ze[(r0 + g) * NDIM + t];
    __syncthreads();
    float s[8];
#pragma unroll
    for (int g = 0; g < 8; g++) s[g] = 0.f;
    float cn = 0.f;
#pragma unroll 4
    for (int d = 0; d < NDIM; d++) {
        const float c = cb[d * NK + t];
        cn = fmaf(c, c, cn);
#pragma unroll
        for (int g = 0; g < 8; g++) s[g] = fmaf(zs[g][d], c, s[g]);
    }
    for (int g = 0; g < 8; g++) {
        red[t] = s[g] - 0.5f * cn;
        redi[t] = t;
        __syncthreads();
        for (int off = 256; off > 0; off >>= 1) {
            if (t < off) {
                const float o = red[t + off];
                const int oi = redi[t + off];
                if (o > red[t] || (o == red[t] && oi < redi[t])) { red[t] = o; redi[t] = oi; }
            }
            __syncthreads();
        }
        if (t == 0) g_idx[r0 + g] = redi[0];
        __syncthreads();
    }
}

// ============================================================================
// prototypes: mean of 5 quantized shots, L2-normalized
// ============================================================================
__global__ __launch_bounds__(512) void proto_kernel(const float* __restrict__ cb) {
    const int bw = blockIdx.x, t = threadIdx.x;
    float p = 0.f;
#pragma unroll
    for (int s = 0; s < 5; s++) p += cb[(size_t)t * NK + g_idx[bw * 5 + s]];
    p *= 0.2f;
    __shared__ float red[512];
    red[t] = p * p;
    __syncthreads();
    for (int off = 256; off > 0; off >>= 1) {
        if (t < off) red[t] += red[t + off];
        __syncthreads();
    }
    g_proto[bw * NDIM + t] = p * rsqrtf(red[0]);
}

// ============================================================================
// logits
// ============================================================================
__global__ __launch_bounds__(512) void logits_kernel(
    const float* __restrict__ cb, const float* __restrict__ tptr,
    float* __restrict__ out) {
    const int bq = blockIdx.x, t = threadIdx.x;
    const int b = bq / 75;
    const float v = cb[(size_t)t * NK + g_idx[NSHOT + bq]];
    __shared__ float red[512];
    red[t] = v * v;
    __syncthreads();
    for (int off = 256; off > 0; off >>= 1) {
        if (t < off) red[t] += red[t + off];
        __syncthreads();
    }
    const float vn = v * rsqrtf(red[0]);
    const float temp = *tptr;
    for (int w = 0; w < 5; w++) {
        __syncthreads();
        red[t] = vn * g_proto[(b * 5 + w) * NDIM + t];
        __syncthreads();
        for (int off = 256; off > 0; off >>= 1) {
            if (t < off) red[t] += red[t + off];
            __syncthreads();
        }
        if (t == 0) out[bq * 5 + w] = red[0] * temp;
    }
}

// ============================================================================
extern "C" void kernel_launch(void* const* d_in, const int* in_sizes, int n_in,
                              void* d_out, int out_size) {
    const float* xs   = (const float*)d_in[0];
    const float* xq   = (const float*)d_in[1];
    const float* W    = (const float*)d_in[2];
    const float* bias = (const float*)d_in[3];
    const float* cb   = (const float*)d_in[4];
    const float* temp = (const float*)d_in[5];
    float* out = (float*)d_out;

    cudaFuncSetAttribute(gemm_hmma, cudaFuncAttributeMaxDynamicSharedMemorySize,
                         SMEM_GEMM);

    conv_a<<<(int)(((size_t)MPAD * IN_DIM / 4 + 255) / 256), 256>>>(xs, xq);
    conv_b<<<dim3(IN_DIM / 32, NDIM / 32), 256>>>(W);
    gemm_hmma<<<dim3(NDIM / BN, MPAD / BM, TOTSPLITS), 256, SMEM_GEMM>>>();
    reduce_bias<<<(MROWS * NDIM + 255) / 256, 256>>>(bias);
    nearest_kernel<<<MROWS / 8, 512>>>(cb);
    proto_kernel<<<20, 512>>>(cb);
    logits_kernel<<<300, 512>>>(cb, temp, out);
}